// round 5
// baseline (speedup 1.0000x reference)
#include <cuda_runtime.h>
#include <cuda_bf16.h>

#define N_NODES  50000
#define N_EDGES  1600000
#define BATCH    4
#define T_STEPS  50
#define DT_CONST 0.02f

#define NCTA     296           // 2 CTAs/SM on 148 SMs -> guaranteed co-resident (proven R1/R2)
#define NTHREADS 512
#define CHUNK    169           // ceil(50000/296)
#define TN       (T_STEPS * N_NODES)
#define NQUADS   ((NCTA * NTHREADS) / 4)   // 37888 quads

// ---------------- device scratch (static, no allocation) ----------------
__device__ int      g_deg[N_NODES];
__device__ int      g_rowptr[N_NODES + 1];
__device__ int      g_cursor[N_NODES];
__device__ int      g_rowLo[NQUADS + 1];    // quad -> first row of its contiguous range
__device__ int2     g_ws[N_EDGES];          // {w as bits, src}
__device__ float2   g_ab[N_NODES];          // {alpha, bias}
__device__ float    g_Vf[N_NODES * 4];      // membrane potential, [n][b]
__device__ float4   g_R[2][N_NODES];        // double-buffered relu(v)
__device__ int      g_blockSum[NCTA];
__device__ unsigned g_bar;

// ---------------- grid barrier (monotone counter, reset by init kernel) ----------------
__device__ __forceinline__ void grid_bar(unsigned k) {
    __syncthreads();
    if (threadIdx.x == 0) {
        __threadfence();
        atomicAdd(&g_bar, 1u);
        const unsigned target = k * (unsigned)NCTA;
        while (*(volatile unsigned*)&g_bar < target) { }
    }
    __syncthreads();
}

// ---------------- block-wide inclusive scan (Kogge-Stone in smem) ----------------
__device__ int block_scan_incl(int v) {
    __shared__ int ss[NTHREADS];
    const int tid = threadIdx.x;
    ss[tid] = v;
    __syncthreads();
#pragma unroll
    for (int off = 1; off < NTHREADS; off <<= 1) {
        int t = 0;
        if (tid >= off) t = ss[tid - off];
        __syncthreads();
        if (tid >= off) ss[tid] += t;
        __syncthreads();
    }
    return ss[tid];
}

__device__ __forceinline__ int quad_of_offset(int off) {
    return (int)(((long long)off * NQUADS) / N_EDGES);
}

// ---------------- init kernel: reset per-launch mutable state ----------------
__global__ void init_kernel() {
    int i = blockIdx.x * blockDim.x + threadIdx.x;
    if (i == 0) g_bar = 0u;
    for (int n = i; n < N_NODES; n += gridDim.x * blockDim.x) g_deg[n] = 0;
}

// ---------------- main persistent kernel ----------------
__global__ void __launch_bounds__(NTHREADS, 2) net_kernel(
    const float* __restrict__ x,       // [B, T, N]
    const float* __restrict__ bias,    // [N]
    const float* __restrict__ tconst,  // [N]
    const float* __restrict__ sign,    // [E]
    const float* __restrict__ cnt,     // [E]
    const float* __restrict__ strg,    // [E]
    const int*   __restrict__ src,     // [E]
    const int*   __restrict__ tgt,     // [E]
    float*       __restrict__ out)     // [B, T, N]
{
    const int tid  = threadIdx.x;
    const int bid  = blockIdx.x;
    const int gtid = bid * NTHREADS + tid;
    const int nthr = NCTA * NTHREADS;
    unsigned barK = 0;

    // ---- Pass A: degree histogram over targets ----
    for (int e = gtid; e < N_EDGES; e += nthr)
        atomicAdd(&g_deg[tgt[e]], 1);
    grid_bar(++barK);

    // ---- Pass B1: per-CTA chunk sums ----
    {
        const int n = bid * CHUNK + tid;
        int v = (tid < CHUNK && n < N_NODES) ? g_deg[n] : 0;
        int incl = block_scan_incl(v);
        if (tid == NTHREADS - 1) g_blockSum[bid] = incl;
    }
    grid_bar(++barK);

    // ---- Pass B2: CTA0 exclusive-scans the block sums ----
    if (bid == 0) {
        int v = (tid < NCTA) ? g_blockSum[tid] : 0;
        int incl = block_scan_incl(v);
        if (tid < NCTA) g_blockSum[tid] = incl - v;
    }
    grid_bar(++barK);

    // ---- Pass B3: per-chunk exclusive scan -> row_ptr & cursor ----
    {
        const int n = bid * CHUNK + tid;
        int v = (tid < CHUNK && n < N_NODES) ? g_deg[n] : 0;
        int incl = block_scan_incl(v);
        if (tid < CHUNK && n < N_NODES) {
            int rp = g_blockSum[bid] + incl - v;
            g_rowptr[n] = rp;
            g_cursor[n] = rp;
        }
        if (gtid == 0) g_rowptr[N_NODES] = N_EDGES;
    }
    grid_bar(++barK);

    // ---- Pass C: scatter edges into CSR slots, fused weight compute ----
    for (int e = gtid; e < N_EDGES; e += nthr) {
        float w = sign[e] * fmaxf(cnt[e], 0.0f) * fmaxf(strg[e], 0.0f);
        int  t = tgt[e];
        int  p = atomicAdd(&g_cursor[t], 1);
        g_ws[p] = make_int2(__float_as_int(w), src[e]);
    }

    // ---- Edge-balanced quad->row-range partition ----
    // rowLo[q] = first row of quad q's contiguous range; rowLo[NQUADS] = N_NODES.
    // Clamp to NQUADS-1 so trailing zero-degree rows still land in the last quad.
    for (int r = gtid; r <= N_NODES; r += nthr) {
        int a, b;
        if (r == N_NODES) {
            a = min(quad_of_offset(g_rowptr[N_NODES - 1]), NQUADS - 1) + 1;
            b = NQUADS;
        } else {
            b = min(quad_of_offset(g_rowptr[r]), NQUADS - 1);
            a = (r == 0) ? 0 : min(quad_of_offset(g_rowptr[r - 1]), NQUADS - 1) + 1;
        }
        for (int qq = a; qq <= b; qq++) g_rowLo[qq] = r;
    }

    // ---- Pass D: node state init (v = bias, rates0 = relu(bias), alpha/bias) ----
    for (int n = gtid; n < N_NODES; n += nthr) {
        float b   = bias[n];
        float tau = fmaxf(tconst[n], DT_CONST);
        g_ab[n] = make_float2(DT_CONST / tau, b);
        float r = fmaxf(b, 0.0f);
        g_Vf[4 * n + 0] = b; g_Vf[4 * n + 1] = b;
        g_Vf[4 * n + 2] = b; g_Vf[4 * n + 3] = b;
        g_R[0][n] = make_float4(r, r, r, r);
    }
    grid_bar(++barK);

    // ---- Hot loop: 50 steps, quad-per-row-range gather SpMV + Euler update ----
    const int q    = tid & 3;         // lane within quad == batch index
    const int qid  = gtid >> 2;       // quad id
    const int rowA = g_rowLo[qid];
    const int rowB = g_rowLo[qid + 1];
    // 4-lane quad mask: quads in a warp have DIFFERENT trip counts, so shuffles
    // must name only the quad's lanes (which do share identical rowA/rowB).
    const unsigned qmask = 0xFu << (tid & 28);

    for (int t = 0; t < T_STEPS; t++) {
        const float4* __restrict__ Rc  = g_R[t & 1];
        float*        __restrict__ Rnf = (float*)(g_R[(t + 1) & 1]);
        const float*  __restrict__ xt  = x + t * N_NODES;
        float*        __restrict__ ot  = out + t * N_NODES;

        for (int r = rowA; r < rowB; ++r) {
            const int beg = g_rowptr[r];          // L1-hit (same addr each step)
            const int end = g_rowptr[r + 1];
            const float xv = __ldcg(xt + q * TN + r);

            unsigned long long a01 = 0ull, a23 = 0ull;   // f32x2 accumulators
#pragma unroll 4
            for (int e = beg + q; e < end; e += 4) {
                int2 ws = g_ws[e];                // L1-resident after step 1
                unsigned long long w2, r01, r23;
                asm("mov.b64 %0, {%1, %1};" : "=l"(w2) : "r"(ws.x));
                asm volatile("ld.global.cg.v2.b64 {%0, %1}, [%2];"
                             : "=l"(r01), "=l"(r23) : "l"(Rc + ws.y));
                asm("fma.rn.f32x2 %0, %1, %2, %3;" : "=l"(a01) : "l"(w2), "l"(r01), "l"(a01));
                asm("fma.rn.f32x2 %0, %1, %2, %3;" : "=l"(a23) : "l"(w2), "l"(r23), "l"(a23));
            }
            // quad reduction with quad-local mask (lanes of a quad are convergent)
#pragma unroll
            for (int off = 1; off < 4; off <<= 1) {
                unsigned long long b01 = __shfl_xor_sync(qmask, a01, off);
                unsigned long long b23 = __shfl_xor_sync(qmask, a23, off);
                asm("add.rn.f32x2 %0, %1, %2;" : "=l"(a01) : "l"(a01), "l"(b01));
                asm("add.rn.f32x2 %0, %1, %2;" : "=l"(a23) : "l"(a23), "l"(b23));
            }
            unsigned long long sel = (q < 2) ? a01 : a23;
            float lo, hi;
            asm("mov.b64 {%0, %1}, %2;" : "=f"(lo), "=f"(hi) : "l"(sel));
            float acc = (q & 1) ? hi : lo;

            float2 ab = g_ab[r];                  // L1-hit
            float  v  = g_Vf[4 * r + q];          // L1-hit
            v = fmaf(ab.x, (ab.y - v) + (acc + xv), v);
            g_Vf[4 * r + q] = v;
            float rr = fmaxf(v, 0.0f);
            Rnf[4 * r + q]  = rr;
            ot[q * TN + r]  = rr;
        }
        if (t != T_STEPS - 1) grid_bar(++barK);
    }
}

extern "C" void kernel_launch(void* const* d_in, const int* in_sizes, int n_in,
                              void* d_out, int out_size) {
    const float* x      = (const float*)d_in[0];
    const float* bias   = (const float*)d_in[1];
    const float* tconst = (const float*)d_in[2];
    const float* sign   = (const float*)d_in[3];
    const float* cnt    = (const float*)d_in[4];
    const float* strg   = (const float*)d_in[5];
    const int*   src    = (const int*)d_in[6];
    const int*   tgt    = (const int*)d_in[7];
    float*       out    = (float*)d_out;

    init_kernel<<<128, 512>>>();
    net_kernel<<<NCTA, NTHREADS>>>(x, bias, tconst, sign, cnt, strg, src, tgt, out);
}

// round 6
// speedup vs baseline: 1.0602x; 1.0602x over previous
#include <cuda_runtime.h>
#include <cuda_bf16.h>

#define N_NODES  50000
#define N_EDGES  1600000
#define BATCH    4
#define T_STEPS  50
#define DT_CONST 0.02f

#define NCTA     444           // 3 CTAs/SM on 148 SMs (launch_bounds contract enforces fit)
#define NTHREADS 512
#define CHUNK    113           // ceil(50000/444)
#define TN       (T_STEPS * N_NODES)
#define QPC      (NTHREADS / 4)              // 128 quads per CTA
#define NQUADS   (NCTA * QPC)                // 56832 quads
#define ECAP     4096                        // smem edge capacity per CTA (32KB)

// ---------------- device scratch (static, no allocation) ----------------
__device__ int      g_deg[N_NODES];
__device__ int      g_rowptr[N_NODES + 1];
__device__ int      g_cursor[N_NODES];
__device__ int      g_rowLo[NQUADS + 1];    // quad -> first row of its contiguous range
__device__ int2     g_ws[N_EDGES];          // {w as bits, src}
__device__ float2   g_ab[N_NODES];          // {alpha, bias}
__device__ float    g_Vf[N_NODES * 4];      // membrane potential, [n][b]
__device__ float4   g_R[2][N_NODES];        // double-buffered relu(v)
__device__ int      g_blockSum[NCTA];
__device__ unsigned g_bar;

// ---------------- grid barrier (monotone counter, reset by init kernel) ----------------
__device__ __forceinline__ void grid_bar(unsigned k) {
    __syncthreads();
    if (threadIdx.x == 0) {
        __threadfence();
        atomicAdd(&g_bar, 1u);
        const unsigned target = k * (unsigned)NCTA;
        while (*(volatile unsigned*)&g_bar < target) { }
    }
    __syncthreads();
}

// ---------------- block-wide inclusive scan (Kogge-Stone in smem) ----------------
__device__ int block_scan_incl(int v) {
    __shared__ int ss[NTHREADS];
    const int tid = threadIdx.x;
    ss[tid] = v;
    __syncthreads();
#pragma unroll
    for (int off = 1; off < NTHREADS; off <<= 1) {
        int t = 0;
        if (tid >= off) t = ss[tid - off];
        __syncthreads();
        if (tid >= off) ss[tid] += t;
        __syncthreads();
    }
    return ss[tid];
}

__device__ __forceinline__ int quad_of_offset(int off) {
    return (int)(((long long)off * NQUADS) / N_EDGES);
}

// ---------------- init kernel: reset per-launch mutable state ----------------
__global__ void init_kernel() {
    int i = blockIdx.x * blockDim.x + threadIdx.x;
    if (i == 0) g_bar = 0u;
    for (int n = i; n < N_NODES; n += gridDim.x * blockDim.x) g_deg[n] = 0;
}

// ---------------- hot loop body, templated on edge source ----------------
template <bool USE_SMEM>
__device__ __forceinline__ void run_steps(
    const int2* __restrict__ s_ws, int ebase,
    int rowA, int rowB, int q, unsigned qmask,
    const float* __restrict__ x, float* __restrict__ out,
    unsigned& barK)
{
    for (int t = 0; t < T_STEPS; t++) {
        const float4* __restrict__ Rc  = g_R[t & 1];
        float*        __restrict__ Rnf = (float*)(g_R[(t + 1) & 1]);
        const float*  __restrict__ xt  = x + t * N_NODES;
        float*        __restrict__ ot  = out + t * N_NODES;

        for (int r = rowA; r < rowB; ++r) {
            const int beg = g_rowptr[r];          // L1-hit (same addr each step)
            const int end = g_rowptr[r + 1];
            const float xv = __ldcg(xt + q * TN + r);

            unsigned long long a01 = 0ull, a23 = 0ull;   // f32x2 accumulators
#pragma unroll 4
            for (int e = beg + q; e < end; e += 4) {
                int2 ws = USE_SMEM ? s_ws[e - ebase] : __ldg(&g_ws[e]);
                unsigned long long w2, r01, r23;
                asm("mov.b64 %0, {%1, %1};" : "=l"(w2) : "r"(ws.x));
                asm volatile("ld.global.cg.v2.b64 {%0, %1}, [%2];"
                             : "=l"(r01), "=l"(r23) : "l"(Rc + ws.y));
                asm("fma.rn.f32x2 %0, %1, %2, %3;" : "=l"(a01) : "l"(w2), "l"(r01), "l"(a01));
                asm("fma.rn.f32x2 %0, %1, %2, %3;" : "=l"(a23) : "l"(w2), "l"(r23), "l"(a23));
            }
            // quad reduction with quad-local mask (quads diverge; quad lanes don't)
#pragma unroll
            for (int off = 1; off < 4; off <<= 1) {
                unsigned long long b01 = __shfl_xor_sync(qmask, a01, off);
                unsigned long long b23 = __shfl_xor_sync(qmask, a23, off);
                asm("add.rn.f32x2 %0, %1, %2;" : "=l"(a01) : "l"(a01), "l"(b01));
                asm("add.rn.f32x2 %0, %1, %2;" : "=l"(a23) : "l"(a23), "l"(b23));
            }
            unsigned long long sel = (q < 2) ? a01 : a23;
            float lo, hi;
            asm("mov.b64 {%0, %1}, %2;" : "=f"(lo), "=f"(hi) : "l"(sel));
            float acc = (q & 1) ? hi : lo;

            float2 ab = g_ab[r];                  // L1-hit
            float  v  = g_Vf[4 * r + q];          // L1-hit
            v = fmaf(ab.x, (ab.y - v) + (acc + xv), v);
            g_Vf[4 * r + q] = v;
            float rr = fmaxf(v, 0.0f);
            Rnf[4 * r + q]  = rr;
            ot[q * TN + r]  = rr;
        }
        if (t != T_STEPS - 1) grid_bar(++barK);
    }
}

// ---------------- main persistent kernel ----------------
__global__ void __launch_bounds__(NTHREADS, 3) net_kernel(
    const float* __restrict__ x,       // [B, T, N]
    const float* __restrict__ bias,    // [N]
    const float* __restrict__ tconst,  // [N]
    const float* __restrict__ sign,    // [E]
    const float* __restrict__ cnt,     // [E]
    const float* __restrict__ strg,    // [E]
    const int*   __restrict__ src,     // [E]
    const int*   __restrict__ tgt,     // [E]
    float*       __restrict__ out)     // [B, T, N]
{
    __shared__ int2 s_ws[ECAP];        // this CTA's edge slice (32KB)

    const int tid  = threadIdx.x;
    const int bid  = blockIdx.x;
    const int gtid = bid * NTHREADS + tid;
    const int nthr = NCTA * NTHREADS;
    unsigned barK = 0;

    // ---- Pass A: degree histogram over targets ----
    for (int e = gtid; e < N_EDGES; e += nthr)
        atomicAdd(&g_deg[tgt[e]], 1);
    grid_bar(++barK);

    // ---- Pass B1: per-CTA chunk sums ----
    {
        const int n = bid * CHUNK + tid;
        int v = (tid < CHUNK && n < N_NODES) ? g_deg[n] : 0;
        int incl = block_scan_incl(v);
        if (tid == NTHREADS - 1) g_blockSum[bid] = incl;
    }
    grid_bar(++barK);

    // ---- Pass B2: CTA0 exclusive-scans the block sums ----
    if (bid == 0) {
        int v = (tid < NCTA) ? g_blockSum[tid] : 0;
        int incl = block_scan_incl(v);
        if (tid < NCTA) g_blockSum[tid] = incl - v;
    }
    grid_bar(++barK);

    // ---- Pass B3: per-chunk exclusive scan -> row_ptr & cursor ----
    {
        const int n = bid * CHUNK + tid;
        int v = (tid < CHUNK && n < N_NODES) ? g_deg[n] : 0;
        int incl = block_scan_incl(v);
        if (tid < CHUNK && n < N_NODES) {
            int rp = g_blockSum[bid] + incl - v;
            g_rowptr[n] = rp;
            g_cursor[n] = rp;
        }
        if (gtid == 0) g_rowptr[N_NODES] = N_EDGES;
    }
    grid_bar(++barK);

    // ---- Pass C: scatter edges into CSR slots, fused weight compute ----
    for (int e = gtid; e < N_EDGES; e += nthr) {
        float w = sign[e] * fmaxf(cnt[e], 0.0f) * fmaxf(strg[e], 0.0f);
        int  t = tgt[e];
        int  p = atomicAdd(&g_cursor[t], 1);
        g_ws[p] = make_int2(__float_as_int(w), src[e]);
    }

    // ---- Edge-balanced quad->row-range partition ----
    for (int r = gtid; r <= N_NODES; r += nthr) {
        int a, b;
        if (r == N_NODES) {
            a = min(quad_of_offset(g_rowptr[N_NODES - 1]), NQUADS - 1) + 1;
            b = NQUADS;
        } else {
            b = min(quad_of_offset(g_rowptr[r]), NQUADS - 1);
            a = (r == 0) ? 0 : min(quad_of_offset(g_rowptr[r - 1]), NQUADS - 1) + 1;
        }
        for (int qq = a; qq <= b; qq++) g_rowLo[qq] = r;
    }

    // ---- Pass D: node state init ----
    for (int n = gtid; n < N_NODES; n += nthr) {
        float b   = bias[n];
        float tau = fmaxf(tconst[n], DT_CONST);
        g_ab[n] = make_float2(DT_CONST / tau, b);
        float r = fmaxf(b, 0.0f);
        g_Vf[4 * n + 0] = b; g_Vf[4 * n + 1] = b;
        g_Vf[4 * n + 2] = b; g_Vf[4 * n + 3] = b;
        g_R[0][n] = make_float4(r, r, r, r);
    }
    grid_bar(++barK);   // edges + partition + state all visible now

    // ---- Stage this CTA's edge slice into shared memory ----
    const int rowA_cta = g_rowLo[bid * QPC];
    const int rowB_cta = g_rowLo[(bid + 1) * QPC];
    const int ebase    = g_rowptr[rowA_cta];
    const int ecnt     = g_rowptr[rowB_cta] - ebase;
    const bool fits    = (ecnt <= ECAP);
    if (fits) {
        for (int i = tid; i < ecnt; i += NTHREADS)
            s_ws[i] = g_ws[ebase + i];
    }
    __syncthreads();

    // ---- Hot loop ----
    const int q    = tid & 3;
    const int qid  = gtid >> 2;
    const int rowA = g_rowLo[qid];
    const int rowB = g_rowLo[qid + 1];
    const unsigned qmask = 0xFu << (tid & 28);

    if (fits)
        run_steps<true >(s_ws, ebase, rowA, rowB, q, qmask, x, out, barK);
    else
        run_steps<false>(s_ws, ebase, rowA, rowB, q, qmask, x, out, barK);
}

extern "C" void kernel_launch(void* const* d_in, const int* in_sizes, int n_in,
                              void* d_out, int out_size) {
    const float* x      = (const float*)d_in[0];
    const float* bias   = (const float*)d_in[1];
    const float* tconst = (const float*)d_in[2];
    const float* sign   = (const float*)d_in[3];
    const float* cnt    = (const float*)d_in[4];
    const float* strg   = (const float*)d_in[5];
    const int*   src    = (const int*)d_in[6];
    const int*   tgt    = (const int*)d_in[7];
    float*       out    = (float*)d_out;

    init_kernel<<<128, 512>>>();
    net_kernel<<<NCTA, NTHREADS>>>(x, bias, tconst, sign, cnt, strg, src, tgt, out);
}